// round 2
// baseline (speedup 1.0000x reference)
#include <cuda_runtime.h>
#include <math.h>
#include <stdint.h>

#define MROWS  16384
#define LSEQ   4096
#define BSZ    4
#define DIMC   384
#define DINNER 768
#define DSTATE 16
#define DTRANK 24

// ---------------- scratch (device globals; allocation-free) ----------------
__device__ float g_Wr_t  [768*384];
__device__ float g_Win_t [384*1536];
__device__ float g_Winb_t[384*768];
__device__ float g_Winc_t[384*768];
__device__ float g_Wxp_t [768*40];
__device__ float g_Wxpc_t[768*16];
__device__ float g_Wdt_t [24*768];
__device__ float g_Wout_t[768*384];

__device__ float g_msn   [MROWS*384];
__device__ float g_pann  [MROWS*384];
__device__ float g_red   [MROWS*384];
__device__ float g_conn  [MROWS*384];
__device__ float g_xz    [(size_t)MROWS*1536];
__device__ float g_xbp   [MROWS*768];
__device__ float g_xcp   [MROWS*768];
__device__ float g_x     [MROWS*768];
__device__ float g_xb    [MROWS*768];
__device__ float g_xc    [MROWS*768];
__device__ float g_dbl   [MROWS*40];
__device__ float g_dt    [MROWS*768];
__device__ float g_cm    [MROWS*16];
__device__ float g_y     [MROWS*768];
__device__ float g_gf    [MROWS*384];
__device__ float g_img   [MROWS*384];

// ---------------- helpers ----------------
__device__ __forceinline__ float silu_f(float v) {
    return v / (1.f + __expf(-v));
}
__device__ __forceinline__ uint32_t f2tf32(float f) {
    uint32_t u;
    asm("cvt.rna.tf32.f32 %0, %1;" : "=r"(u) : "f"(f));
    return u;
}

#define MMA_TF32(c0,c1,c2,c3, a0,a1,a2,a3, b0,b1)                      \
  asm volatile("mma.sync.aligned.m16n8k8.row.col.f32.tf32.tf32.f32 "   \
      "{%0,%1,%2,%3}, {%4,%5,%6,%7}, {%8,%9}, {%0,%1,%2,%3};\n"        \
      : "+f"(c0), "+f"(c1), "+f"(c2), "+f"(c3)                          \
      : "r"(a0), "r"(a1), "r"(a2), "r"(a3), "r"(b0), "r"(b1))

// ---------------- weight transpose: out[k*N+n] = in[n*K+k] ----------------
__global__ void wt_transpose(const float* __restrict__ in, float* __restrict__ out,
                             int N, int K) {
    int idx = blockIdx.x * blockDim.x + threadIdx.x;
    if (idx >= N * K) return;
    int n = idx % N;
    int k = idx / N;
    out[(size_t)k * N + n] = in[(size_t)n * K + k];
}

// ---------------- layernorm over 384, one block (128 thr) per row ----------------
__global__ __launch_bounds__(128) void ln_kernel(const float* __restrict__ x,
                                                 const float* __restrict__ w,
                                                 const float* __restrict__ b,
                                                 float* __restrict__ out) {
    int m = blockIdx.x;
    int t = threadIdx.x;
    const float* row = x + (size_t)m * 384;
    float v0 = row[t], v1 = row[t + 128], v2 = row[t + 256];
    float s = v0 + v1 + v2;
    __shared__ float red1[4], red2[4];
    #pragma unroll
    for (int o = 16; o; o >>= 1) s += __shfl_xor_sync(0xffffffffu, s, o);
    if ((t & 31) == 0) red1[t >> 5] = s;
    __syncthreads();
    float mu = (red1[0] + red1[1] + red1[2] + red1[3]) * (1.f / 384.f);
    float d0 = v0 - mu, d1 = v1 - mu, d2 = v2 - mu;
    float q = d0 * d0 + d1 * d1 + d2 * d2;
    #pragma unroll
    for (int o = 16; o; o >>= 1) q += __shfl_xor_sync(0xffffffffu, q, o);
    if ((t & 31) == 0) red2[t >> 5] = q;
    __syncthreads();
    float var = (red2[0] + red2[1] + red2[2] + red2[3]) * (1.f / 384.f);
    float inv = rsqrtf(var + 1e-5f);
    float* o = out + (size_t)m * 384;
    o[t]       = d0 * inv * w[t]       + b[t];
    o[t + 128] = d1 * inv * w[t + 128] + b[t + 128];
    o[t + 256] = d2 * inv * w[t + 256] + b[t + 256];
}

// ---------------- TF32 tensor-core GEMM ----------------
// C[M,N] = A[M,K] * Bt[K,N]  (+bias, +resid). M,N multiples of 128, K mult of 16.
// Optional split-A: columns k >= ksplit come from A2 (concat fusion).
// Block 256 thr = 8 warps (4x2), tile 128x128, BK=16, double buffered.
__global__ __launch_bounds__(256) void gemm_tf32(
    const float* __restrict__ A, int lda,
    const float* __restrict__ A2, int lda2, int ksplit,
    const float* __restrict__ Bt,
    const float* __restrict__ bias,
    const float* __restrict__ resid, int ldr,
    float* __restrict__ C, int ldc,
    int N, int K)
{
    __shared__ float As[2][16][128];   // k-major, col swizz: m ^ ((k&3)<<3)
    __shared__ float Bs[2][16][128];   // n swizz: n ^ ((k&3)<<3)
    const int tid  = threadIdx.x;
    const int lane = tid & 31;
    const int wid  = tid >> 5;
    const int g    = lane >> 2;
    const int tig  = lane & 3;
    const int warp_m = wid & 3;
    const int warp_n = wid >> 2;
    const int bm = blockIdx.y * 128;
    const int bn = blockIdx.x * 128;

    // loader mapping
    const int am  = tid >> 1;          // 0..127 (A row within tile)
    const int ak  = (tid & 1) * 4;     // A k-quad base (then +8 for p=1)
    const int bk  = tid >> 5;          // 0..7 (B k-row, then +8)
    const int bj4 = (tid & 31) * 4;    // B col quad

    float acc[2][8][4];
    #pragma unroll
    for (int i = 0; i < 2; i++)
        #pragma unroll
        for (int j = 0; j < 8; j++)
            #pragma unroll
            for (int q = 0; q < 4; q++) acc[i][j][q] = 0.f;

    const int ktiles = K / 16;
    float4 av[2], bv[2];

    // ---- fetch tile 0 ----
    #pragma unroll
    for (int p = 0; p < 2; ++p) {
        int gk = ak + p * 8;
        const float* src = (A2 != nullptr && gk >= ksplit)
            ? (A2 + (size_t)(bm + am) * lda2 + (gk - ksplit))
            : (A  + (size_t)(bm + am) * lda  + gk);
        av[p] = *(const float4*)src;
        int gkb = bk + p * 8;
        bv[p] = *(const float4*)(Bt + (size_t)gkb * N + bn + bj4);
    }
    // ---- store tile 0 ----
    #pragma unroll
    for (int p = 0; p < 2; ++p) {
        int k0 = ak + p * 8;
        As[0][k0 + 0][am ^ 0 ] = __uint_as_float(f2tf32(av[p].x));
        As[0][k0 + 1][am ^ 8 ] = __uint_as_float(f2tf32(av[p].y));
        As[0][k0 + 2][am ^ 16] = __uint_as_float(f2tf32(av[p].z));
        As[0][k0 + 3][am ^ 24] = __uint_as_float(f2tf32(av[p].w));
        int kb2 = bk + p * 8;
        int cj = bj4 ^ ((kb2 & 3) << 3);
        float4 bw;
        bw.x = __uint_as_float(f2tf32(bv[p].x));
        bw.y = __uint_as_float(f2tf32(bv[p].y));
        bw.z = __uint_as_float(f2tf32(bv[p].z));
        bw.w = __uint_as_float(f2tf32(bv[p].w));
        *(float4*)&Bs[0][kb2][cj] = bw;
    }
    __syncthreads();

    for (int t = 0; t < ktiles; ++t) {
        int buf = t & 1;
        // prefetch next tile into regs
        if (t + 1 < ktiles) {
            int kbase = (t + 1) * 16;
            #pragma unroll
            for (int p = 0; p < 2; ++p) {
                int gk = kbase + ak + p * 8;
                const float* src = (A2 != nullptr && gk >= ksplit)
                    ? (A2 + (size_t)(bm + am) * lda2 + (gk - ksplit))
                    : (A  + (size_t)(bm + am) * lda  + gk);
                av[p] = *(const float4*)src;
                int gkb = kbase + bk + p * 8;
                bv[p] = *(const float4*)(Bt + (size_t)gkb * N + bn + bj4);
            }
        }
        // compute on buf
        #pragma unroll
        for (int ks = 0; ks < 2; ++ks) {
            int kb2 = ks * 8;
            int klo = kb2 + tig;
            int khi = kb2 + tig + 4;
            int sw = tig << 3;
            uint32_t afr[2][4];
            #pragma unroll
            for (int mt = 0; mt < 2; ++mt) {
                int m0 = warp_m * 32 + mt * 16;
                afr[mt][0] = __float_as_uint(As[buf][klo][(m0 + g    ) ^ sw]);
                afr[mt][1] = __float_as_uint(As[buf][klo][(m0 + g + 8) ^ sw]);
                afr[mt][2] = __float_as_uint(As[buf][khi][(m0 + g    ) ^ sw]);
                afr[mt][3] = __float_as_uint(As[buf][khi][(m0 + g + 8) ^ sw]);
            }
            uint32_t bfr[8][2];
            #pragma unroll
            for (int nt = 0; nt < 8; ++nt) {
                int n0 = (warp_n * 64 + nt * 8 + g) ^ sw;
                bfr[nt][0] = __float_as_uint(Bs[buf][klo][n0]);
                bfr[nt][1] = __float_as_uint(Bs[buf][khi][n0]);
            }
            #pragma unroll
            for (int mt = 0; mt < 2; ++mt)
                #pragma unroll
                for (int nt = 0; nt < 8; ++nt)
                    MMA_TF32(acc[mt][nt][0], acc[mt][nt][1], acc[mt][nt][2], acc[mt][nt][3],
                             afr[mt][0], afr[mt][1], afr[mt][2], afr[mt][3],
                             bfr[nt][0], bfr[nt][1]);
        }
        // store prefetched tile
        if (t + 1 < ktiles) {
            int nb = buf ^ 1;
            #pragma unroll
            for (int p = 0; p < 2; ++p) {
                int k0 = ak + p * 8;
                As[nb][k0 + 0][am ^ 0 ] = __uint_as_float(f2tf32(av[p].x));
                As[nb][k0 + 1][am ^ 8 ] = __uint_as_float(f2tf32(av[p].y));
                As[nb][k0 + 2][am ^ 16] = __uint_as_float(f2tf32(av[p].z));
                As[nb][k0 + 3][am ^ 24] = __uint_as_float(f2tf32(av[p].w));
                int kb2 = bk + p * 8;
                int cj = bj4 ^ ((kb2 & 3) << 3);
                float4 bw;
                bw.x = __uint_as_float(f2tf32(bv[p].x));
                bw.y = __uint_as_float(f2tf32(bv[p].y));
                bw.z = __uint_as_float(f2tf32(bv[p].z));
                bw.w = __uint_as_float(f2tf32(bv[p].w));
                *(float4*)&Bs[nb][kb2][cj] = bw;
            }
        }
        __syncthreads();
    }

    // epilogue
    #pragma unroll
    for (int mt = 0; mt < 2; ++mt) {
        int r0 = bm + warp_m * 32 + mt * 16 + g;
        int r1 = r0 + 8;
        #pragma unroll
        for (int nt = 0; nt < 8; ++nt) {
            int n0 = bn + warp_n * 64 + nt * 8 + tig * 2;
            float2 v0 = make_float2(acc[mt][nt][0], acc[mt][nt][1]);
            float2 v1 = make_float2(acc[mt][nt][2], acc[mt][nt][3]);
            if (bias) {
                float2 bb = *(const float2*)&bias[n0];
                v0.x += bb.x; v0.y += bb.y;
                v1.x += bb.x; v1.y += bb.y;
            }
            if (resid) {
                float2 e0 = *(const float2*)&resid[(size_t)r0 * ldr + n0];
                float2 e1 = *(const float2*)&resid[(size_t)r1 * ldr + n0];
                v0.x += e0.x; v0.y += e0.y;
                v1.x += e1.x; v1.y += e1.y;
            }
            *(float2*)&C[(size_t)r0 * ldc + n0] = v0;
            *(float2*)&C[(size_t)r1 * ldc + n0] = v1;
        }
    }
}

// ---------------- fp32 SGEMM (small N / small K cases) ----------------
__global__ __launch_bounds__(256) void sgemm(
    const float* __restrict__ A, int lda,
    const float* __restrict__ Bt,
    const float* __restrict__ bias,
    float* __restrict__ C, int ldc,
    int M, int N, int K, int act)
{
    __shared__ float As[8][132];
    __shared__ float Bs[8][128];
    int tid = threadIdx.x;
    int bm = blockIdx.y * 128, bn = blockIdx.x * 128;
    int row = tid / 16, col = tid % 16;

    float acc[8][8];
    #pragma unroll
    for (int i = 0; i < 8; i++)
        #pragma unroll
        for (int j = 0; j < 8; j++) acc[i][j] = 0.f;

    int a_m = tid / 2;
    int a_k = (tid % 2) * 4;
    int b_n = (tid % 32) * 4;
    int b_k = tid / 32;

    int ktiles = (K + 7) / 8;
    for (int t = 0; t < ktiles; ++t) {
        int k0 = t * 8;
        {
            float4 av = make_float4(0.f, 0.f, 0.f, 0.f);
            int gm = bm + a_m, gk = k0 + a_k;
            const float* ap = A + (size_t)gm * lda;
            if (gk + 3 < K) {
                av = *(const float4*)(ap + gk);
            } else {
                if (gk + 0 < K) av.x = ap[gk + 0];
                if (gk + 1 < K) av.y = ap[gk + 1];
                if (gk + 2 < K) av.z = ap[gk + 2];
                if (gk + 3 < K) av.w = ap[gk + 3];
            }
            As[a_k + 0][a_m] = av.x;
            As[a_k + 1][a_m] = av.y;
            As[a_k + 2][a_m] = av.z;
            As[a_k + 3][a_m] = av.w;
        }
        {
            float4 bvv = make_float4(0.f, 0.f, 0.f, 0.f);
            int gn = bn + b_n, gk = k0 + b_k;
            if (gk < K) {
                const float* bp = Bt + (size_t)gk * N;
                if (gn + 3 < N) {
                    bvv = *(const float4*)(bp + gn);
                } else {
                    if (gn + 0 < N) bvv.x = bp[gn + 0];
                    if (gn + 1 < N) bvv.y = bp[gn + 1];
                    if (gn + 2 < N) bvv.z = bp[gn + 2];
                    if (gn + 3 < N) bvv.w = bp[gn + 3];
                }
            }
            *(float4*)&Bs[b_k][b_n] = bvv;
        }
        __syncthreads();
        #pragma unroll
        for (int k = 0; k < 8; ++k) {
            float a[8], b[8];
            *(float4*)(a)     = *(const float4*)&As[k][row * 8];
            *(float4*)(a + 4) = *(const float4*)&As[k][row * 8 + 4];
            *(float4*)(b)     = *(const float4*)&Bs[k][col * 8];
            *(float4*)(b + 4) = *(const float4*)&Bs[k][col * 8 + 4];
            #pragma unroll
            for (int i = 0; i < 8; i++)
                #pragma unroll
                for (int j = 0; j < 8; j++)
                    acc[i][j] = fmaf(a[i], b[j], acc[i][j]);
        }
        __syncthreads();
    }
    #pragma unroll
    for (int i = 0; i < 8; i++) {
        int m = bm + row * 8 + i;
        if (m >= M) continue;
        #pragma unroll
        for (int j = 0; j < 8; j++) {
            int n = bn + col * 8 + j;
            if (n >= N) continue;
            float v = acc[i][j];
            if (bias) v += bias[n];
            if (act == 1) {
                v = (v > 20.f) ? v : log1pf(expf(v));
            }
            C[(size_t)m * ldc + n] = v;
        }
    }
}

// ---------------- causal depthwise conv1d (K=4) + SiLU ----------------
__global__ void dwconv1d_silu(const float* __restrict__ x, int xstride,
                              const float* __restrict__ w,
                              const float* __restrict__ bias,
                              float* __restrict__ out) {
    int idx = blockIdx.x * blockDim.x + threadIdx.x;
    if (idx >= MROWS * DINNER) return;
    int d = idx % DINNER;
    int m = idx / DINNER;
    int l = m & (LSEQ - 1);
    float acc = bias[d];
    #pragma unroll
    for (int k = 0; k < 4; k++) {
        int ll = l - 3 + k;
        if (ll >= 0)
            acc += w[d * 4 + k] * x[(size_t)(m + (ll - l)) * xstride + d];
    }
    out[(size_t)m * DINNER + d] = silu_f(acc);
}

// ---------------- selective scan (+ fused silu(z) gate) ----------------
__global__ __launch_bounds__(256) void scan_kernel(
    const float* __restrict__ u,
    const float* __restrict__ dt,
    const float* __restrict__ dbl,
    const float* __restrict__ Cm,
    const float* __restrict__ A_log,
    const float* __restrict__ Dp,
    const float* __restrict__ xz,   // z at column offset 768, stride 1536
    float* __restrict__ y)
{
    int b  = blockIdx.x / 48;
    int d0 = (blockIdx.x % 48) * 16;
    int tid = threadIdx.x;
    int dl = tid / 16;
    int n  = tid % 16;
    int d = d0 + dl;
    float a = -expf(A_log[d * 16 + n]);
    float Dv = Dp[d];
    __shared__ float sdt[16][16], su[16][16], sB[16][17], sC[16][17];
    float h = 0.f;
    size_t base = (size_t)b * LSEQ;
    int lo = tid / 16, c = tid % 16;
    for (int l0 = 0; l0 < LSEQ; l0 += 16) {
        size_t m = base + l0 + lo;
        sdt[lo][c] = dt[m * 768 + d0 + c];
        su [lo][c] = u [m * 768 + d0 + c];
        sB [lo][c] = dbl[m * 40 + 24 + c];
        sC [lo][c] = Cm [m * 16 + c];
        __syncthreads();
        #pragma unroll
        for (int s = 0; s < 16; ++s) {
            float dtv = sdt[s][dl];
            float uv  = su [s][dl];
            float Bv  = sB [s][n];
            float Cv  = sC [s][n];
            h = expf(dtv * a) * h + dtv * uv * Bv;
            float p = h * Cv;
            p += __shfl_xor_sync(0xffffffffu, p, 8);
            p += __shfl_xor_sync(0xffffffffu, p, 4);
            p += __shfl_xor_sync(0xffffffffu, p, 2);
            p += __shfl_xor_sync(0xffffffffu, p, 1);
            if (n == 0) {
                size_t mm = base + l0 + s;
                float z = xz[mm * 1536 + 768 + d];
                y[mm * 768 + d] = (p + uv * Dv) * silu_f(z);
            }
        }
        __syncthreads();
    }
}

// ---------------- (B,L,C) -> (B,C,L) transpose ----------------
__global__ void transpose_LC(const float* __restrict__ in, float* __restrict__ out) {
    __shared__ float t[32][33];
    int bb = blockIdx.z;
    int c0 = blockIdx.x * 32, l0 = blockIdx.y * 32;
    const float* ip = in + (size_t)bb * LSEQ * DIMC;
    float* op = out + (size_t)bb * DIMC * LSEQ;
    int tx = threadIdx.x, ty = threadIdx.y;
    #pragma unroll
    for (int i = 0; i < 32; i += 8)
        t[ty + i][tx] = ip[(size_t)(l0 + ty + i) * DIMC + c0 + tx];
    __syncthreads();
    #pragma unroll
    for (int i = 0; i < 32; i += 8)
        op[(size_t)(c0 + ty + i) * LSEQ + l0 + tx] = t[tx][ty + i];
}

// ---------------- final 3x3 depthwise conv (SAME) on (B,C,64,64) ----------------
__global__ void dwconv3x3(const float* __restrict__ img, const float* __restrict__ w,
                          const float* __restrict__ bias, float* __restrict__ out) {
    int idx = blockIdx.x * blockDim.x + threadIdx.x;
    if (idx >= BSZ * DIMC * 64 * 64) return;
    int wv = idx & 63;
    int h  = (idx >> 6) & 63;
    int c  = (idx >> 12) % DIMC;
    int b  = idx / (DIMC * 4096);
    const float* ip = img + ((size_t)b * DIMC + c) * 4096;
    const float* wc = w + c * 9;
    float acc = bias[c];
    #pragma unroll
    for (int dh = -1; dh <= 1; dh++) {
        int hh = h + dh;
        if (hh < 0 || hh >= 64) continue;
        #pragma unroll
        for (int dw = -1; dw <= 1; dw++) {
            int ww = wv + dw;
            if (ww < 0 || ww >= 64) continue;
            acc += wc[(dh + 1) * 3 + (dw + 1)] * ip[hh * 64 + ww];
        }
    }
    out[idx] = acc;
}

// ---------------- host ----------------
static void launch_tf32(const float* A, int lda,
                        const float* A2, int lda2, int ksplit,
                        const float* Bt, const float* bias,
                        const float* resid, int ldr,
                        float* C, int ldc, int M, int N, int K) {
    dim3 grid(N / 128, M / 128);
    gemm_tf32<<<grid, 256>>>(A, lda, A2, lda2, ksplit, Bt, bias, resid, ldr,
                             C, ldc, N, K);
}

extern "C" void kernel_launch(void* const* d_in, const int* in_sizes, int n_in,
                              void* d_out, int out_size) {
    const float* ms          = (const float*)d_in[0];
    const float* pan         = (const float*)d_in[1];
    const float* reduce_W    = (const float*)d_in[2];
    const float* reduce_b    = (const float*)d_in[3];
    const float* ln1_w       = (const float*)d_in[4];
    const float* ln1_b       = (const float*)d_in[5];
    const float* ln2_w       = (const float*)d_in[6];
    const float* ln2_b       = (const float*)d_in[7];
    const float* ln3_w       = (const float*)d_in[8];
    const float* ln3_b       = (const float*)d_in[9];
    const float* in_proj_W   = (const float*)d_in[10];
    const float* in_proj_b_W = (const float*)d_in[11];
    const float* in_proj_c_W = (const float*)d_in[12];
    const float* conv_w      = (const float*)d_in[13];
    const float* conv_bias   = (const float*)d_in[14];
    const float* conv_b_w    = (const float*)d_in[15];
    const float* conv_b_bias = (const float*)d_in[16];
    const float* conv_c_w    = (const float*)d_in[17];
    const float* conv_c_bias = (const float*)d_in[18];
    const float* x_proj_W    = (const float*)d_in[19];
    const float* x_proj_c_W  = (const float*)d_in[20];
    const float* dt_proj_W   = (const float*)d_in[21];
    const float* dt_proj_bias= (const float*)d_in[22];
    const float* A_log       = (const float*)d_in[23];
    const float* Dvec        = (const float*)d_in[24];
    const float* out_proj_W  = (const float*)d_in[25];
    const float* dwconv_w    = (const float*)d_in[26];
    const float* dwconv_b    = (const float*)d_in[27];
    float* out = (float*)d_out;

    float *pWr, *pWin, *pWinb, *pWinc, *pWxp, *pWxpc, *pWdt, *pWout;
    float *pmsn, *ppann, *pred, *pconn, *pxz, *pxbp, *pxcp;
    float *px, *pxb, *pxc, *pdbl, *pdt, *pcm, *py, *pgf, *pimg;
    cudaGetSymbolAddress((void**)&pWr,   g_Wr_t);
    cudaGetSymbolAddress((void**)&pWin,  g_Win_t);
    cudaGetSymbolAddress((void**)&pWinb, g_Winb_t);
    cudaGetSymbolAddress((void**)&pWinc, g_Winc_t);
    cudaGetSymbolAddress((void**)&pWxp,  g_Wxp_t);
    cudaGetSymbolAddress((void**)&pWxpc, g_Wxpc_t);
    cudaGetSymbolAddress((void**)&pWdt,  g_Wdt_t);
    cudaGetSymbolAddress((void**)&pWout, g_Wout_t);
    cudaGetSymbolAddress((void**)&pmsn,  g_msn);
    cudaGetSymbolAddress((void**)&ppann, g_pann);
    cudaGetSymbolAddress((void**)&pred,  g_red);
    cudaGetSymbolAddress((void**)&pconn, g_conn);
    cudaGetSymbolAddress((void**)&pxz,   g_xz);
    cudaGetSymbolAddress((void**)&pxbp,  g_xbp);
    cudaGetSymbolAddress((void**)&pxcp,  g_xcp);
    cudaGetSymbolAddress((void**)&px,    g_x);
    cudaGetSymbolAddress((void**)&pxb,   g_xb);
    cudaGetSymbolAddress((void**)&pxc,   g_xc);
    cudaGetSymbolAddress((void**)&pdbl,  g_dbl);
    cudaGetSymbolAddress((void**)&pdt,   g_dt);
    cudaGetSymbolAddress((void**)&pcm,   g_cm);
    cudaGetSymbolAddress((void**)&py,    g_y);
    cudaGetSymbolAddress((void**)&pgf,   g_gf);
    cudaGetSymbolAddress((void**)&pimg,  g_img);

    auto wt = [](const float* in, float* o, int N, int K) {
        int tot = N * K;
        wt_transpose<<<(tot + 255) / 256, 256>>>(in, o, N, K);
    };
    wt(reduce_W,    pWr,   384, 768);
    wt(in_proj_W,   pWin,  1536, 384);
    wt(in_proj_b_W, pWinb, 768, 384);
    wt(in_proj_c_W, pWinc, 768, 384);
    wt(x_proj_W,    pWxp,  40, 768);
    wt(x_proj_c_W,  pWxpc, 16, 768);
    wt(dt_proj_W,   pWdt,  768, 24);
    wt(out_proj_W,  pWout, 384, 768);

    // reduce GEMM with fused concat (A = [ms | pan])
    launch_tf32(ms, 384, pan, 384, 384, pWr, reduce_b, nullptr, 0,
                pred, 384, MROWS, 384, 768);
    ln_kernel<<<MROWS, 128>>>(ms,   ln1_w, ln1_b, pmsn);
    ln_kernel<<<MROWS, 128>>>(pan,  ln2_w, ln2_b, ppann);
    ln_kernel<<<MROWS, 128>>>(pred, ln3_w, ln3_b, pconn);

    // big projections (TF32 tensor cores)
    launch_tf32(pmsn,  384, nullptr, 0, 1 << 30, pWin,  nullptr, nullptr, 0,
                pxz, 1536, MROWS, 1536, 384);
    launch_tf32(ppann, 384, nullptr, 0, 1 << 30, pWinb, nullptr, nullptr, 0,
                pxbp, 768, MROWS, 768, 384);
    launch_tf32(pconn, 384, nullptr, 0, 1 << 30, pWinc, nullptr, nullptr, 0,
                pxcp, 768, MROWS, 768, 384);

    // depthwise causal convs + SiLU
    {
        int tot = MROWS * DINNER;
        int blocks = (tot + 255) / 256;
        dwconv1d_silu<<<blocks, 256>>>(pxz,  1536, conv_w,   conv_bias,   px);
        dwconv1d_silu<<<blocks, 256>>>(pxbp, 768,  conv_b_w, conv_b_bias, pxb);
        dwconv1d_silu<<<blocks, 256>>>(pxcp, 768,  conv_c_w, conv_c_bias, pxc);
    }

    // small projections (fp32)
    {
        dim3 g1((40 + 127) / 128, MROWS / 128);
        sgemm<<<g1, 256>>>(pxb, 768, pWxp, nullptr, pdbl, 40, MROWS, 40, 768, 0);
        dim3 g2((16 + 127) / 128, MROWS / 128);
        sgemm<<<g2, 256>>>(pxc, 768, pWxpc, nullptr, pcm, 16, MROWS, 16, 768, 0);
        dim3 g3((768 + 127) / 128, MROWS / 128);
        sgemm<<<g3, 256>>>(pdbl, 40, pWdt, dt_proj_bias, pdt, 768, MROWS, 768, 24, 1);
    }

    // selective scan with fused gate
    scan_kernel<<<BSZ * 48, 256>>>(px, pdt, pdbl, pcm, A_log, Dvec, pxz, py);

    // out_proj + residual(ms)
    launch_tf32(py, 768, nullptr, 0, 1 << 30, pWout, nullptr, ms, 384,
                pgf, 384, MROWS, 384, 768);

    // (B,L,C) -> (B,C,HW) transpose, then 3x3 depthwise conv
    {
        dim3 grid(DIMC / 32, LSEQ / 32, BSZ);
        dim3 blk(32, 8);
        transpose_LC<<<grid, blk>>>(pgf, pimg);
    }
    {
        int tot = BSZ * DIMC * 64 * 64;
        dwconv3x3<<<(tot + 255) / 256, 256>>>(pimg, dwconv_w, dwconv_b, out);
    }
}

// round 4
// speedup vs baseline: 1.1045x; 1.1045x over previous
#include <cuda_runtime.h>
#include <cuda_bf16.h>
#include <math.h>
#include <stdint.h>

#define MROWS  16384
#define LSEQ   4096
#define BSZ    4
#define DIMC   384
#define DINNER 768
#define DSTATE 16
#define DTRANK 24

typedef __nv_bfloat16 bf16;

// ---------------- scratch (device globals; allocation-free) ----------------
__device__ bf16 g_Wr16  [384*768];
__device__ bf16 g_Win16 [1536*384];
__device__ bf16 g_Winb16[768*384];
__device__ bf16 g_Winc16[768*384];
__device__ bf16 g_Wout16[384*768];
__device__ float g_Wxp_t [768*40];
__device__ float g_Wxpc_t[768*16];
__device__ float g_Wdt_t [24*768];
__device__ bf16 g_ms16  [MROWS*384];
__device__ bf16 g_pan16 [MROWS*384];
__device__ bf16 g_msn16 [MROWS*384];
__device__ bf16 g_pann16[MROWS*384];
__device__ bf16 g_conn16[MROWS*384];
__device__ bf16 g_y16   [MROWS*768];
__device__ float g_red  [MROWS*384];
__device__ float g_xz   [(size_t)MROWS*1536];
__device__ float g_xbp  [MROWS*768];
__device__ float g_xcp  [MROWS*768];
__device__ float g_x    [MROWS*768];
__device__ float g_xb   [MROWS*768];
__device__ float g_xc   [MROWS*768];
__device__ float g_dbl  [MROWS*40];
__device__ float g_dt   [MROWS*768];
__device__ float g_cm   [MROWS*16];
__device__ float g_gf   [MROWS*384];
__device__ float g_img  [MROWS*384];

// ---------------- helpers ----------------
__device__ __forceinline__ float silu_f(float v) {
    return v / (1.f + __expf(-v));
}
__device__ __forceinline__ uint32_t smem_u32(const void* p) {
    uint32_t a;
    asm("{ .reg .u64 t; cvta.to.shared.u64 t, %1; cvt.u32.u64 %0, t; }"
        : "=r"(a) : "l"(p));
    return a;
}

#define CP_ASYNC16(dst, src) \
    asm volatile("cp.async.cg.shared.global [%0], [%1], 16;" :: "r"(dst), "l"(src))
#define CP_COMMIT() asm volatile("cp.async.commit_group;" ::: "memory")

#define LDSM_X4(r, addr)                                                     \
    asm volatile("ldmatrix.sync.aligned.m8n8.x4.shared.b16 {%0,%1,%2,%3}, [%4];" \
        : "=r"((r)[0]), "=r"((r)[1]), "=r"((r)[2]), "=r"((r)[3]) : "r"(addr))

#define MMA_BF16(c, a, b0, b1)                                               \
    asm volatile("mma.sync.aligned.m16n8k16.row.col.f32.bf16.bf16.f32 "      \
        "{%0,%1,%2,%3}, {%4,%5,%6,%7}, {%8,%9}, {%0,%1,%2,%3};"              \
        : "+f"((c)[0]), "+f"((c)[1]), "+f"((c)[2]), "+f"((c)[3])             \
        : "r"((a)[0]), "r"((a)[1]), "r"((a)[2]), "r"((a)[3]),                \
          "r"(b0), "r"(b1))

// ---------------- fp32 -> bf16 convert ----------------
__global__ void f2bf(const float4* __restrict__ in, __nv_bfloat162* __restrict__ out, int n4) {
    int i = blockIdx.x * blockDim.x + threadIdx.x;
    if (i >= n4) return;
    float4 v = in[i];
    out[i * 2 + 0] = __floats2bfloat162_rn(v.x, v.y);
    out[i * 2 + 1] = __floats2bfloat162_rn(v.z, v.w);
}

// ---------------- weight transpose (small fp32 GEMMs) ----------------
__global__ void wt_transpose(const float* __restrict__ in, float* __restrict__ out,
                             int N, int K) {
    int idx = blockIdx.x * blockDim.x + threadIdx.x;
    if (idx >= N * K) return;
    int n = idx % N;
    int k = idx / N;
    out[(size_t)k * N + n] = in[(size_t)n * K + k];
}

// ---------------- layernorm over 384 -> bf16 out ----------------
__global__ __launch_bounds__(128) void ln_kernel(const float* __restrict__ x,
                                                 const float* __restrict__ w,
                                                 const float* __restrict__ b,
                                                 bf16* __restrict__ out) {
    int m = blockIdx.x;
    int t = threadIdx.x;
    const float* row = x + (size_t)m * 384;
    float v0 = row[t], v1 = row[t + 128], v2 = row[t + 256];
    float s = v0 + v1 + v2;
    __shared__ float red1[4], red2[4];
    #pragma unroll
    for (int o = 16; o; o >>= 1) s += __shfl_xor_sync(0xffffffffu, s, o);
    if ((t & 31) == 0) red1[t >> 5] = s;
    __syncthreads();
    float mu = (red1[0] + red1[1] + red1[2] + red1[3]) * (1.f / 384.f);
    float d0 = v0 - mu, d1 = v1 - mu, d2 = v2 - mu;
    float q = d0 * d0 + d1 * d1 + d2 * d2;
    #pragma unroll
    for (int o = 16; o; o >>= 1) q += __shfl_xor_sync(0xffffffffu, q, o);
    if ((t & 31) == 0) red2[t >> 5] = q;
    __syncthreads();
    float var = (red2[0] + red2[1] + red2[2] + red2[3]) * (1.f / 384.f);
    float inv = rsqrtf(var + 1e-5f);
    bf16* o = out + (size_t)m * 384;
    o[t]       = __float2bfloat16_rn(d0 * inv * w[t]       + b[t]);
    o[t + 128] = __float2bfloat16_rn(d1 * inv * w[t + 128] + b[t + 128]);
    o[t + 256] = __float2bfloat16_rn(d2 * inv * w[t + 256] + b[t + 256]);
}

// ---------------- bf16 mma.sync GEMM ----------------
// C[M,N] = A[M,K](bf16) @ Bw[N,K](bf16)^T (+bias fp32, +resid fp32)
// 128x128 tile, BK=32, 8 warps (4x2), ldmatrix + m16n8k16, cp.async double buffer.
// Smem rows padded to 40 bf16 (80B): conflict-free ldmatrix.
#define SROW 40

__global__ __launch_bounds__(256) void gemm_mma(
    const bf16* __restrict__ A, int lda,
    const bf16* __restrict__ A2, int lda2, int ksplit,
    const bf16* __restrict__ Bw, int ldb,
    const float* __restrict__ bias,
    const float* __restrict__ resid, int ldr,
    float* __restrict__ C, int ldc, int K)
{
    __shared__ bf16 sA[2][128 * SROW];
    __shared__ bf16 sB[2][128 * SROW];
    const int tid = threadIdx.x;
    const int lane = tid & 31;
    const int wid = tid >> 5;
    const int wm = (wid & 3) * 32;
    const int wn = (wid >> 2) * 64;
    const int bm = blockIdx.y * 128;
    const int bn = blockIdx.x * 128;

    const uint32_t sAaddr = smem_u32(sA);
    const uint32_t sBaddr = smem_u32(sB);

    float acc[2][8][4];
    #pragma unroll
    for (int i = 0; i < 2; i++)
        #pragma unroll
        for (int j = 0; j < 8; j++)
            #pragma unroll
            for (int q = 0; q < 4; q++) acc[i][j][q] = 0.f;

    const int nk = K >> 5;  // BK=32
    const int lrow = tid >> 2;           // 0..63 (2 iters -> 128 rows)
    const int lch  = (tid & 3) * 8;      // k element offset (8 bf16 = 16B)

    auto load_tile = [&](int kc, int buf) {
        const int kg = kc * 32;
        const bf16* Asrc; int alds, aoff;
        if (A2 != nullptr && kg >= ksplit) { Asrc = A2; alds = lda2; aoff = kg - ksplit; }
        else                               { Asrc = A;  alds = lda;  aoff = kg; }
        #pragma unroll
        for (int i = 0; i < 2; i++) {
            int row = lrow + i * 64;
            uint32_t da = sAaddr + (uint32_t)buf * (128 * SROW * 2)
                        + (row * SROW + lch) * 2;
            uint32_t db = sBaddr + (uint32_t)buf * (128 * SROW * 2)
                        + (row * SROW + lch) * 2;
            CP_ASYNC16(da, Asrc + (size_t)(bm + row) * alds + aoff + lch);
            CP_ASYNC16(db, Bw   + (size_t)(bn + row) * ldb  + kg   + lch);
        }
        CP_COMMIT();
    };

    load_tile(0, 0);
    load_tile(1, 1);

    // ldmatrix per-thread address components
    const int a_row = wm + (lane & 15);
    const int a_k   = (lane >> 4) << 3;
    const int b_row = wn + (((lane >> 4) & 1) << 3) + (lane & 7);
    const int b_k   = ((lane >> 3) & 1) << 3;

    for (int kc = 0; kc < nk; ++kc) {
        if (kc == nk - 1) asm volatile("cp.async.wait_group 0;" ::: "memory");
        else              asm volatile("cp.async.wait_group 1;" ::: "memory");
        __syncthreads();
        const int buf = kc & 1;
        const uint32_t aBase = sAaddr + (uint32_t)buf * (128 * SROW * 2)
                             + (a_row * SROW + a_k) * 2;
        const uint32_t bBase = sBaddr + (uint32_t)buf * (128 * SROW * 2)
                             + (b_row * SROW + b_k) * 2;
        #pragma unroll
        for (int ks = 0; ks < 2; ++ks) {
            uint32_t a0[4], a1[4];
            LDSM_X4(a0, aBase + ks * 32);
            LDSM_X4(a1, aBase + ks * 32 + 16 * SROW * 2);
            #pragma unroll
            for (int nt2 = 0; nt2 < 4; ++nt2) {
                uint32_t b[4];
                LDSM_X4(b, bBase + ks * 32 + nt2 * 16 * SROW * 2);
                MMA_BF16(acc[0][nt2 * 2],     a0, b[0], b[1]);
                MMA_BF16(acc[0][nt2 * 2 + 1], a0, b[2], b[3]);
                MMA_BF16(acc[1][nt2 * 2],     a1, b[0], b[1]);
                MMA_BF16(acc[1][nt2 * 2 + 1], a1, b[2], b[3]);
            }
        }
        __syncthreads();
        if (kc + 2 < nk) load_tile(kc + 2, buf);
    }

    // epilogue
    #pragma unroll
    for (int mt = 0; mt < 2; ++mt) {
        int r0 = bm + wm + mt * 16 + (lane >> 2);
        int r1 = r0 + 8;
        #pragma unroll
        for (int nt = 0; nt < 8; ++nt) {
            int n0 = bn + wn + nt * 8 + (lane & 3) * 2;
            float2 v0 = make_float2(acc[mt][nt][0], acc[mt][nt][1]);
            float2 v1 = make_float2(acc[mt][nt][2], acc[mt][nt][3]);
            if (bias) {
                float2 bb = *(const float2*)&bias[n0];
                v0.x += bb.x; v0.y += bb.y;
                v1.x += bb.x; v1.y += bb.y;
            }
            if (resid) {
                float2 e0 = *(const float2*)&resid[(size_t)r0 * ldr + n0];
                float2 e1 = *(const float2*)&resid[(size_t)r1 * ldr + n0];
                v0.x += e0.x; v0.y += e0.y;
                v1.x += e1.x; v1.y += e1.y;
            }
            *(float2*)&C[(size_t)r0 * ldc + n0] = v0;
            *(float2*)&C[(size_t)r1 * ldc + n0] = v1;
        }
    }
}

// ---------------- fp32 SGEMM (small N / small K cases) ----------------
__global__ __launch_bounds__(256) void sgemm(
    const float* __restrict__ A, int lda,
    const float* __restrict__ Bt,
    const float* __restrict__ bias,
    float* __restrict__ C, int ldc,
    int M, int N, int K, int act)
{
    __shared__ float As[8][132];
    __shared__ float Bs[8][128];
    int tid = threadIdx.x;
    int bm = blockIdx.y * 128, bn = blockIdx.x * 128;
    int row = tid / 16, col = tid % 16;

    float acc[8][8];
    #pragma unroll
    for (int i = 0; i < 8; i++)
        #pragma unroll
        for (int j = 0; j < 8; j++) acc[i][j] = 0.f;

    int a_m = tid / 2;
    int a_k = (tid % 2) * 4;
    int b_n = (tid % 32) * 4;
    int b_k = tid / 32;

    int ktiles = (K + 7) / 8;
    for (int t = 0; t < ktiles; ++t) {
        int k0 = t * 8;
        {
            float4 av = make_float4(0.f, 0.f, 0.f, 0.f);
            int gm = bm + a_m, gk = k0 + a_k;
            const float* ap = A + (size_t)gm * lda;
            if (gk + 3 < K) {
                av = *(const float4*)(ap + gk);
            } else {
                if (gk + 0 < K) av.x = ap[gk + 0];
                if (gk + 1 < K) av.y = ap[gk + 1];
                if (gk + 2 < K) av.z = ap[gk + 2];
                if (gk + 3 < K) av.w = ap[gk + 3];
            }
            As[a_k + 0][a_m] = av.x;
            As[a_k + 1][a_m] = av.y;
            As[a_k + 2][a_m] = av.z;
            As[a_k + 3][a_m] = av.w;
        }
        {
            float4 bvv = make_float4(0.f, 0.f, 0.f, 0.f);
            int gn = bn + b_n, gk = k0 + b_k;
            if (gk < K) {
                const float* bp = Bt + (size_t)gk * N;
                if (gn + 3 < N) {
                    bvv = *(const float4*)(bp + gn);
                } else {
                    if (gn + 0 < N) bvv.x = bp[gn + 0];
                    if (gn + 1 < N) bvv.y = bp[gn + 1];
                    if (gn + 2 < N) bvv.z = bp[gn + 2];
                    if (gn + 3 < N) bvv.w = bp[gn + 3];
                }
            }
            *(float4*)&Bs[b_k][b_n] = bvv;
        }
        __syncthreads();
        #pragma unroll
        for (int k = 0; k < 8; ++k) {
            float a[8], b[8];
            *(float4*)(a)     = *(const float4*)&As[k][row * 8];
            *(float4*)(a + 4) = *(const float4*)&As[k][row * 8 + 4];
            *(float4*)(b)     = *(const float4*)&Bs[k][col * 8];
            *(float4*)(b + 4) = *(const float4*)&Bs[k][col * 8 + 4];
            #pragma unroll
            for (int i = 0; i < 8; i++)
                #pragma unroll
                for (int j = 0; j < 8; j++)
                    acc[i][j] = fmaf(a[i], b[j], acc[i][j]);
        }
        __syncthreads();
    }
    #pragma unroll
    for (int i = 0; i < 8; i++) {
        int m = bm + row * 8 + i;
        if (m >= M) continue;
        #pragma unroll
        for (int j = 0; j < 8; j++) {
            int n = bn + col * 8 + j;
            if (n >= N) continue;
            float v = acc[i][j];
            if (bias) v += bias[n];
            if (act == 1) {
                v = (v > 20.f) ? v : log1pf(expf(v));
            }
            C[(size_t)m * ldc + n] = v;
        }
    }
}

// ---------------- causal depthwise conv1d (K=4) + SiLU ----------------
__global__ void dwconv1d_silu(const float* __restrict__ x, int xstride,
                              const float* __restrict__ w,
                              const float* __restrict__ bias,
                              float* __restrict__ out) {
    int idx = blockIdx.x * blockDim.x + threadIdx.x;
    if (idx >= MROWS * DINNER) return;
    int d = idx % DINNER;
    int m = idx / DINNER;
    int l = m & (LSEQ - 1);
    float acc = bias[d];
    #pragma unroll
    for (int k = 0; k < 4; k++) {
        int ll = l - 3 + k;
        if (ll >= 0)
            acc += w[d * 4 + k] * x[(size_t)(m + (ll - l)) * xstride + d];
    }
    out[(size_t)m * DINNER + d] = silu_f(acc);
}

// ---------------- selective scan (+ fused silu(z) gate), bf16 output ----------------
__global__ __launch_bounds__(256) void scan_kernel(
    const float* __restrict__ u,
    const float* __restrict__ dt,
    const float* __restrict__ dbl,
    const float* __restrict__ Cm,
    const float* __restrict__ A_log,
    const float* __restrict__ Dp,
    const float* __restrict__ xz,
    bf16* __restrict__ y)
{
    int b  = blockIdx.x / 48;
    int d0 = (blockIdx.x % 48) * 16;
    int tid = threadIdx.x;
    int dl = tid / 16;
    int n  = tid % 16;
    int d = d0 + dl;
    float a = -expf(A_log[d * 16 + n]);
    float Dv = Dp[d];
    __shared__ float sdt[16][16], su[16][16], sB[16][17], sC[16][17];
    float h = 0.f;
    size_t base = (size_t)b * LSEQ;
    int lo = tid / 16, c = tid % 16;
    for (int l0 = 0; l0 < LSEQ; l0 += 16) {
        size_t m = base + l0 + lo;
        sdt[lo][c] = dt[m * 768 + d0 + c];
        su [lo][c] = u [m * 768 + d0 + c];
        sB [lo][c] = dbl[m * 40 + 24 + c];
        sC [lo][c] = Cm [m * 16 + c];
        __syncthreads();
        #pragma unroll
        for (int s = 0; s < 16; ++s) {
            float dtv = sdt[s][dl];
            float uv  = su [s][dl];
            float Bv  = sB [s][n];
            float Cv  = sC [s][n];
            h = expf(dtv * a) * h + dtv * uv * Bv;
            float p = h * Cv;
            p += __shfl_xor_sync(0xffffffffu, p, 8);
            p += __shfl_xor_sync(0xffffffffu, p, 4);
            p += __shfl_xor_sync(0xffffffffu, p, 2);
            p += __shfl_xor_sync(0xffffffffu, p, 1);
            if (n == 0) {
                size_t mm = base + l0 + s;
                float z = xz[mm * 1536 + 768 + d];
                y[mm * 768 + d] = __float2bfloat16_rn((p + uv * Dv) * silu_f(z));
            }
        }
        __syncthreads();
    }
}

// ---------------- (B,L,C) -> (B,C,L) transpose ----------------
__global__ void transpose_LC(const float* __restrict__ in, float* __restrict__ out) {
    __shared__ float t[32][33];
    int bb = blockIdx.z;
    int c0 = blockIdx.x * 32, l0 = blockIdx.y * 32;
    const float* ip = in + (size_t)bb * LSEQ * DIMC;
    float* op = out + (size_t)bb * DIMC * LSEQ;
    int tx = threadIdx.x, ty = threadIdx.y;
    #pragma unroll
    for (int i = 0; i < 32; i += 8)
        t[ty + i][tx] = ip[(size_t)(l0 + ty + i) * DIMC + c0 + tx];
    __syncthreads();
    #pragma unroll
    for (int i = 0; i < 32; i += 8)
        op[(size_t)(c0 + ty + i) * LSEQ + l0 + tx] = t[tx][ty + i];
}

// ---------------- final 3x3 depthwise conv (SAME) on (B,C,64,64) ----------------
__global__ void dwconv3x3(const float* __restrict__ img, const float* __restrict__ w,
                          const float* __restrict__ bias, float* __restrict__ out) {
    int idx = blockIdx.x * blockDim.x + threadIdx.x;
    if (idx >= BSZ * DIMC * 64 * 64) return;
    int wv = idx & 63;
    int h  = (idx >> 6) & 63;
    int c  = (idx >> 12) % DIMC;
    int b  = idx / (DIMC * 4096);
    const float* ip = img + ((size_t)b * DIMC + c) * 4096;
    const float* wc = w + c * 9;
    float acc = bias[c];
    #pragma unroll
    for (int dh = -1; dh <= 1; dh++) {
        int hh = h + dh;
        if (hh < 0 || hh >= 64) continue;
        #pragma unroll
        for (int dw = -1; dw <= 1; dw++) {
            int ww = wv + dw;
            if (ww < 0 || ww >= 64) continue;
            acc += wc[(dh + 1) * 3 + (dw + 1)] * ip[hh * 64 + ww];
        }
    }
    out[idx] = acc;
}

// ---------------- host ----------------
static void launch_gmma(const bf16* A, int lda, const bf16* A2, int lda2, int ksplit,
                        const bf16* Bw, int ldb, const float* bias,
                        const float* resid, int ldr,
                        float* C, int ldc, int M, int N, int K) {
    dim3 grid(N / 128, M / 128);
    gemm_mma<<<grid, 256>>>(A, lda, A2, lda2, ksplit, Bw, ldb,
                            bias, resid, ldr, C, ldc, K);
}

extern "C" void kernel_launch(void* const* d_in, const int* in_sizes, int n_in,
                              void* d_out, int out_size) {
    const float* ms          = (const float*)d_in[0];
    const float* pan         = (const float*)d_in[1];
    const float* reduce_W    = (const float*)d_in[2];
    const float* reduce_b    = (const float*)d_in[3];
    const float* ln1_w       = (const float*)d_in[4];
    const float* ln1_b       = (const float*)d_in[5];
    const float* ln2_w       = (const float*)d_in[6];
    const float* ln2_b       = (const float*)d_in[7];
    const float* ln3_w       = (const float*)d_in[8];
    const float* ln3_b       = (const float*)d_in[9];
    const float* in_proj_W   = (const float*)d_in[10];
    const float* in_proj_b_W = (const float*)d_in[11];
    const float* in_proj_c_W = (const float*)d_in[12];
    const float* conv_w      = (const float*)d_in[13];
    const float* conv_bias   = (const float*)d_in[14];
    const float* conv_b_w    = (const float*)d_in[15];
    const float* conv_b_bias = (const float*)d_in[16];
    const float* conv_c_w    = (const float*)d_in[17];
    const float* conv_c_bias = (const float*)d_in[18];
    const float* x_proj_W    = (const float*)d_in[19];
    const float* x_proj_c_W  = (const float*)d_in[20];
    const float* dt_proj_W   = (const float*)d_in[21];
    const float* dt_proj_bias= (const float*)d_in[22];
    const float* A_log       = (const float*)d_in[23];
    const float* Dvec        = (const float*)d_in[24];
    const float* out_proj_W  = (const float*)d_in[25];
    const float* dwconv_w    = (const float*)d_in[26];
    const float* dwconv_b    = (const float*)d_in[27];
    float* out = (float*)d_out;

    bf16 *pWr16, *pWin16, *pWinb16, *pWinc16, *pWout16;
    bf16 *pms16, *ppan16, *pmsn16, *ppann16, *pconn16, *py16;
    float *pWxp, *pWxpc, *pWdt;
    float *pred, *pxz, *pxbp, *pxcp, *px, *pxb, *pxc, *pdbl, *pdt, *pcm, *pgf, *pimg;
    cudaGetSymbolAddress((void**)&pWr16,   g_Wr16);
    cudaGetSymbolAddress((void**)&pWin16,  g_Win16);
    cudaGetSymbolAddress((void**)&pWinb16, g_Winb16);
    cudaGetSymbolAddress((void**)&pWinc16, g_Winc16);
    cudaGetSymbolAddress((void**)&pWout16, g_Wout16);
    cudaGetSymbolAddress((void**)&pms16,   g_ms16);
    cudaGetSymbolAddress((void**)&ppan16,  g_pan16);
    cudaGetSymbolAddress((void**)&pmsn16,  g_msn16);
    cudaGetSymbolAddress((void**)&ppann16, g_pann16);
    cudaGetSymbolAddress((void**)&pconn16, g_conn16);
    cudaGetSymbolAddress((void**)&py16,    g_y16);
    cudaGetSymbolAddress((void**)&pWxp,    g_Wxp_t);
    cudaGetSymbolAddress((void**)&pWxpc,   g_Wxpc_t);
    cudaGetSymbolAddress((void**)&pWdt,    g_Wdt_t);
    cudaGetSymbolAddress((void**)&pred,    g_red);
    cudaGetSymbolAddress((void**)&pxz,     g_xz);
    cudaGetSymbolAddress((void**)&pxbp,    g_xbp);
    cudaGetSymbolAddress((void**)&pxcp,    g_xcp);
    cudaGetSymbolAddress((void**)&px,      g_x);
    cudaGetSymbolAddress((void**)&pxb,     g_xb);
    cudaGetSymbolAddress((void**)&pxc,     g_xc);
    cudaGetSymbolAddress((void**)&pdbl,    g_dbl);
    cudaGetSymbolAddress((void**)&pdt,     g_dt);
    cudaGetSymbolAddress((void**)&pcm,     g_cm);
    cudaGetSymbolAddress((void**)&pgf,     g_gf);
    cudaGetSymbolAddress((void**)&pimg,    g_img);

    auto cvt = [](const float* in, bf16* o, int n) {
        int n4 = n / 4;
        f2bf<<<(n4 + 255) / 256, 256>>>((const float4*)in, (__nv_bfloat162*)o, n4);
    };

    // launches 1-5 (launch 6 = in_proj mma GEMM, for ncu -s 5 -c 1)
    cvt(ms,  pms16,  MROWS * 384);                        // 1
    cvt(pan, ppan16, MROWS * 384);                        // 2
    cvt(in_proj_W, pWin16, 1536 * 384);                   // 3
    ln_kernel<<<MROWS, 128>>>(ms, ln1_w, ln1_b, pmsn16);  // 4
    cvt(reduce_W, pWr16, 384 * 768);                      // 5

    // 6: in_proj GEMM (profiled by ncu)
    launch_gmma(pmsn16, 384, nullptr, 0, 1 << 30, pWin16, 384,
                nullptr, nullptr, 0, pxz, 1536, MROWS, 1536, 384);

    ln_kernel<<<MROWS, 128>>>(pan, ln2_w, ln2_b, ppann16);  // 7

    // reduce GEMM with fused concat (A = [ms16 | pan16])
    launch_gmma(pms16, 384, ppan16, 384, 384, pWr16, 768,
                reduce_b, nullptr, 0, pred, 384, MROWS, 384, 768);

    ln_kernel<<<MROWS, 128>>>(pred, ln3_w, ln3_b, pconn16);

    cvt(in_proj_b_W, pWinb16, 768 * 384);
    cvt(in_proj_c_W, pWinc16, 768 * 384);
    cvt(out_proj_W,  pWout16, 384 * 768);

    launch_gmma(ppann16, 384, nullptr, 0, 1 << 30, pWinb16, 384,
                nullptr, nullptr, 0, pxbp, 768, MROWS, 768, 384);
    launch_gmma(pconn16, 384, nullptr, 0, 1 << 30, pWinc16, 384,
                nullptr, nullptr, 0, pxcp, 768, MROWS, 768, 384);

    // depthwise causal convs + SiLU
    {
        int tot = MROWS * DINNER;
        int blocks = (tot + 255) / 256;
        dwconv1d_silu<<<blocks, 256>>>(pxz,  1536, conv_w,   conv_bias,   px);
        dwconv1d_silu<<<blocks, 256>>>(pxbp, 768,  conv_b_w, conv_b_bias, pxb);
        dwconv1d_silu<<<blocks, 256>>>(pxcp, 768,  conv_c_w, conv_c_bias, pxc);
    }

    // small weight transposes + fp32 GEMMs
    {
        wt_transpose<<<(40 * 768 + 255) / 256, 256>>>(x_proj_W,   pWxp,  40, 768);
        wt_transpose<<<(16 * 768 + 255) / 256, 256>>>(x_proj_c_W, pWxpc, 16, 768);
        wt_transpose<<<(768 * 24 + 255) / 256, 256>>>(dt_proj_W,  pWdt,  768, 24);
        dim3 g1(1, MROWS / 128);
        sgemm<<<g1, 256>>>(pxb, 768, pWxp, nullptr, pdbl, 40, MROWS, 40, 768, 0);
        dim3 g2(1, MROWS / 128);
        sgemm<<<g2, 256>>>(pxc, 768, pWxpc, nullptr, pcm, 16, MROWS, 16, 768, 0);
        dim3 g3(6, MROWS / 128);
        sgemm<<<g3, 256>>>(pdbl, 40, pWdt, dt_proj_bias, pdt, 768, MROWS, 768, 24, 1);
    }

    // selective scan with fused gate -> bf16 y
    scan_kernel<<<BSZ * 48, 256>>>(px, pdt, pdbl, pcm, A_log, Dvec, pxz, py16);

    // out_proj + residual(ms)
    launch_gmma(py16, 768, nullptr, 0, 1 << 30, pWout16, 768,
                nullptr, ms, 384, pgf, 384, MROWS, 384, 768);

    // (B,L,C) -> (B,C,HW) transpose, then 3x3 depthwise conv
    {
        dim3 grid(DIMC / 32, LSEQ / 32, BSZ);
        dim3 blk(32, 8);
        transpose_LC<<<grid, blk>>>(pgf, pimg);
    }
    {
        int tot = BSZ * DIMC * 64 * 64;
        dwconv3x3<<<(tot + 255) / 256, 256>>>(pimg, dwconv_w, dwconv_b, out);
    }
}